// round 5
// baseline (speedup 1.0000x reference)
#include <cuda_runtime.h>
#include <cstdint>
#include <math.h>

#define BATCH 4
#define SEQ 2048
#define CH 768
#define NHEADS 12
#define HD 64
#define MTOT (BATCH * SEQ)   // 8192
#define C3 (3 * CH)          // 2304

// Scratch (allocation-free contract)
__device__ float g_x[(size_t)MTOT * CH];       // tf32-rounded x
__device__ float g_qkv[(size_t)MTOT * C3];     // tf32-rounded qkv
__device__ float g_att[(size_t)MTOT * CH];     // tf32-rounded attn out
__device__ float g_wqkvT[(size_t)C3 * CH];     // Wqkv^T, tf32-rounded
__device__ float g_wprojT[(size_t)CH * CH];    // Wproj^T, tf32-rounded

__device__ __forceinline__ uint32_t smem_u32(const void* p) {
    uint32_t a;
    asm("{ .reg .u64 t; cvta.to.shared.u64 t, %1; cvt.u32.u64 %0, t; }"
        : "=r"(a) : "l"(p));
    return a;
}
__device__ __forceinline__ float f2tf(float x) {
    unsigned u;
    asm("cvt.rna.tf32.f32 %0, %1;" : "=r"(u) : "f"(x));
    return __uint_as_float(u);
}
#define CP16(dst, src) \
    asm volatile("cp.async.cg.shared.global [%0], [%1], 16;" \
                 :: "r"(dst), "l"(src) : "memory")
#define CP_COMMIT() asm volatile("cp.async.commit_group;" ::: "memory")
#define CP_WAIT(n)  asm volatile("cp.async.wait_group %0;" :: "n"(n) : "memory")

// m16n8k8 tf32 mma, fp32 accumulate in-place.
__device__ __forceinline__ void mma8(float* c, const unsigned* a,
                                     unsigned b0, unsigned b1) {
    asm volatile(
        "mma.sync.aligned.m16n8k8.row.col.f32.tf32.tf32.f32 "
        "{%0,%1,%2,%3}, {%4,%5,%6,%7}, {%8,%9}, {%0,%1,%2,%3};"
        : "+f"(c[0]), "+f"(c[1]), "+f"(c[2]), "+f"(c[3])
        : "r"(a[0]), "r"(a[1]), "r"(a[2]), "r"(a[3]), "r"(b0), "r"(b1));
}

// ---------------------------------------------------------------------------
// Prepass: round x to tf32
// ---------------------------------------------------------------------------
__global__ __launch_bounds__(256) void round_kernel(
    const float* __restrict__ in, float* __restrict__ outp)
{
    const int idx = blockIdx.x * 256 + threadIdx.x;
    float4 v = ((const float4*)in)[idx];
    float4 o = { f2tf(v.x), f2tf(v.y), f2tf(v.z), f2tf(v.w) };
    ((float4*)outp)[idx] = o;
}

// ---------------------------------------------------------------------------
// Weight transpose with tf32 rounding: Wt[n][k] = round(W[k][n])
// ---------------------------------------------------------------------------
__global__ __launch_bounds__(256) void transpose_kernel(
    const float* __restrict__ W, float* __restrict__ Wt, int R, int Cc)
{
    __shared__ float t[32][33];
    const int bx = blockIdx.x * 32, by = blockIdx.y * 32;
    const int x = threadIdx.x & 31, y4 = (threadIdx.x >> 5) * 4;
    #pragma unroll
    for (int j = 0; j < 4; j++)
        t[y4 + j][x] = W[(long)(by + y4 + j) * Cc + bx + x];
    __syncthreads();
    #pragma unroll
    for (int j = 0; j < 4; j++)
        Wt[(long)(bx + y4 + j) * R + by + x] = f2tf(t[x][y4 + j]);
}

// ---------------------------------------------------------------------------
// tf32 mma.sync GEMM + bias (unchanged from R4): C = A @ Bt^T + bias
// ---------------------------------------------------------------------------
#define GSTRIDE 36
#define GTILE (128 * GSTRIDE)

template <bool ROUND>
__global__ __launch_bounds__(256, 2) void gemm_tc(
    const float* __restrict__ A, const float* __restrict__ Bt,
    const float* __restrict__ bias, float* __restrict__ C,
    int M, int N, int K)
{
    extern __shared__ float gsm[];
    const int tid = threadIdx.x;
    const int lane = tid & 31, wid = tid >> 5;
    const int g = lane >> 2, tq = lane & 3;
    const int wm = (wid & 3) * 32, wn = (wid >> 2) * 64;
    const int bm = blockIdx.y * 128, bn = blockIdx.x * 128;
    const int sr = tid >> 3, sc4 = (tid & 7) * 4;

    float acc[2][8][4];
    #pragma unroll
    for (int mt = 0; mt < 2; mt++)
        #pragma unroll
        for (int nt = 0; nt < 8; nt++)
            #pragma unroll
            for (int j = 0; j < 4; j++) acc[mt][nt][j] = 0.f;

    const int NK = K / 32;
    auto issue = [&](int kt, int b) {
        float* As = gsm + b * 2 * GTILE;
        float* Bs = As + GTILE;
        const int k0 = kt * 32;
        #pragma unroll
        for (int i = 0; i < 4; i++) {
            int r = sr + 32 * i;
            CP16(smem_u32(As + r * GSTRIDE + sc4),
                 A + (long)(bm + r) * K + k0 + sc4);
            CP16(smem_u32(Bs + r * GSTRIDE + sc4),
                 Bt + (long)(bn + r) * K + k0 + sc4);
        }
        CP_COMMIT();
    };

    issue(0, 0);
    for (int kt = 0; kt < NK; kt++) {
        const int buf = kt & 1;
        if (kt + 1 < NK) { issue(kt + 1, buf ^ 1); CP_WAIT(1); }
        else             { CP_WAIT(0); }
        __syncthreads();

        const unsigned* As = (const unsigned*)(gsm + buf * 2 * GTILE);
        const unsigned* Bs = As + GTILE;
        #pragma unroll
        for (int ks = 0; ks < 4; ks++) {
            const int kb = ks * 8;
            unsigned af[2][4];
            #pragma unroll
            for (int mt = 0; mt < 2; mt++) {
                int r = wm + mt * 16 + g;
                af[mt][0] = As[r * GSTRIDE + kb + tq];
                af[mt][1] = As[(r + 8) * GSTRIDE + kb + tq];
                af[mt][2] = As[r * GSTRIDE + kb + tq + 4];
                af[mt][3] = As[(r + 8) * GSTRIDE + kb + tq + 4];
            }
            #pragma unroll
            for (int nt = 0; nt < 8; nt++) {
                int c = wn + nt * 8 + g;
                unsigned b0 = Bs[c * GSTRIDE + kb + tq];
                unsigned b1 = Bs[c * GSTRIDE + kb + tq + 4];
                mma8(acc[0][nt], af[0], b0, b1);
                mma8(acc[1][nt], af[1], b0, b1);
            }
        }
        __syncthreads();
    }

    #pragma unroll
    for (int mt = 0; mt < 2; mt++) {
        const long r0 = bm + wm + mt * 16 + g;
        #pragma unroll
        for (int nt = 0; nt < 8; nt++) {
            const int col = bn + wn + nt * 8 + 2 * tq;
            const float bz0 = bias[col], bz1 = bias[col + 1];
            float2 v0 = { acc[mt][nt][0] + bz0, acc[mt][nt][1] + bz1 };
            float2 v1 = { acc[mt][nt][2] + bz0, acc[mt][nt][3] + bz1 };
            if (ROUND) {
                v0.x = f2tf(v0.x); v0.y = f2tf(v0.y);
                v1.x = f2tf(v1.x); v1.y = f2tf(v1.y);
            }
            *(float2*)(C + r0 * N + col)       = v0;
            *(float2*)(C + (r0 + 8) * N + col) = v1;
        }
    }
}

// ---------------------------------------------------------------------------
// Flash attention v2: Br=256, Bc=64, 256 threads (8 warps, 32 rows/warp),
// double-buffered cp.async K/V (prefetch t+2 while computing t), base-2
// softmax (scale*log2e folded into Q staging, exp2f -> bare MUFU EX2).
// Smem: Q 256x68 | P 256x68 | K 2x64x68 | V 2x64x72  = 210944 B (1 CTA/SM).
// ---------------------------------------------------------------------------
#define BR 256
#define QS_OFF 0
#define PS_OFF (BR * 68)
#define KS_OFF (2 * BR * 68)
#define VS_OFF (2 * BR * 68 + 2 * 64 * 68)
#define KBUF (64 * 68)
#define VBUF (64 * 72)
#define FL_WORDS (2 * BR * 68 + 2 * 64 * 68 + 2 * 64 * 72)  // 52736 w = 210944 B
#define NTILES (SEQ / 64)   // 32

__global__ __launch_bounds__(256, 1) void flash_tf32()
{
    extern __shared__ float sm[];
    float* Qs = sm + QS_OFF;
    float* Ps = sm + PS_OFF;

    const int tid = threadIdx.x;
    const int lane = tid & 31, w = tid >> 5;
    const int g = lane >> 2, tq = lane & 3;
    const int b = blockIdx.y / NHEADS, h = blockIdx.y % NHEADS;
    const int q0 = blockIdx.x * BR;
    const long rowbase = (long)b * SEQ;
    const float kscale = 0.125f * 1.44269504089f;   // 1/sqrt(d) * log2(e)

    // Stage Q (scale folded, re-rounded to tf32 so mma truncation is exact)
    #pragma unroll
    for (int i = 0; i < 16; i++) {
        int idx = tid + 256 * i;
        int r = idx >> 4, c4 = (idx & 15) * 4;
        float4 v = *(const float4*)&g_qkv[(rowbase + q0 + r) * C3 + h * HD + c4];
        float* d = Qs + r * 68 + c4;
        d[0] = f2tf(v.x * kscale); d[1] = f2tf(v.y * kscale);
        d[2] = f2tf(v.z * kscale); d[3] = f2tf(v.w * kscale);
    }

    // KV staging: tile t, buffer bf. 64 rows; 4 float4 each for K and V.
    auto issue_kv = [&](int t, int bf) {
        float* Kd = sm + KS_OFF + bf * KBUF;
        float* Vd = sm + VS_OFF + bf * VBUF;
        const int k0 = t * 64;
        #pragma unroll
        for (int i = 0; i < 4; i++) {
            int idx = tid + 256 * i;
            int r = idx >> 4, c4 = (idx & 15) * 4;
            long gb = (rowbase + k0 + r) * C3 + h * HD + c4;
            CP16(smem_u32(Kd + r * 68 + c4), &g_qkv[gb + CH]);
            CP16(smem_u32(Vd + r * 72 + c4), &g_qkv[gb + 2 * CH]);
        }
        CP_COMMIT();
    };

    float o[2][8][4];
    float m_i[2][2], l_i[2][2];
    #pragma unroll
    for (int mt = 0; mt < 2; mt++) {
        m_i[mt][0] = m_i[mt][1] = -1e30f;
        l_i[mt][0] = l_i[mt][1] = 0.f;
        #pragma unroll
        for (int nt = 0; nt < 8; nt++)
            #pragma unroll
            for (int j = 0; j < 4; j++) o[mt][nt][j] = 0.f;
    }

    issue_kv(0, 0);
    issue_kv(1, 1);

    for (int t = 0; t < NTILES; t++) {
        const int buf = t & 1;
        if (t < NTILES - 1) CP_WAIT(1); else CP_WAIT(0);
        __syncthreads();   // KV(t) visible; buffers safe to read

        const unsigned* Qu = (const unsigned*)Qs;
        const unsigned* Ku = (const unsigned*)(sm + KS_OFF + buf * KBUF);
        const unsigned* Vu = (const unsigned*)(sm + VS_OFF + buf * VBUF);

        // S = Q @ K^T : warp rows [32w, 32w+32), 64 kv cols
        float s[2][8][4];
        #pragma unroll
        for (int mt = 0; mt < 2; mt++)
            #pragma unroll
            for (int nt = 0; nt < 8; nt++)
                #pragma unroll
                for (int j = 0; j < 4; j++) s[mt][nt][j] = 0.f;
        #pragma unroll
        for (int ks = 0; ks < 8; ks++) {
            const int kb = ks * 8;
            unsigned af[2][4];
            #pragma unroll
            for (int mt = 0; mt < 2; mt++) {
                int rr = w * 32 + mt * 16 + g;
                af[mt][0] = Qu[rr * 68 + kb + tq];
                af[mt][1] = Qu[(rr + 8) * 68 + kb + tq];
                af[mt][2] = Qu[rr * 68 + kb + tq + 4];
                af[mt][3] = Qu[(rr + 8) * 68 + kb + tq + 4];
            }
            #pragma unroll
            for (int nt = 0; nt < 8; nt++) {
                int c = nt * 8 + g;
                unsigned b0 = Ku[c * 68 + kb + tq];
                unsigned b1 = Ku[c * 68 + kb + tq + 4];
                mma8(s[0][nt], af[0], b0, b1);
                mma8(s[1][nt], af[1], b0, b1);
            }
        }

        // Online softmax (base-2 domain) per 16-row sub-tile
        #pragma unroll
        for (int mt = 0; mt < 2; mt++) {
            float mx0 = -1e30f, mx1 = -1e30f;
            #pragma unroll
            for (int nt = 0; nt < 8; nt++) {
                mx0 = fmaxf(mx0, fmaxf(s[mt][nt][0], s[mt][nt][1]));
                mx1 = fmaxf(mx1, fmaxf(s[mt][nt][2], s[mt][nt][3]));
            }
            mx0 = fmaxf(mx0, __shfl_xor_sync(0xffffffffu, mx0, 1));
            mx0 = fmaxf(mx0, __shfl_xor_sync(0xffffffffu, mx0, 2));
            mx1 = fmaxf(mx1, __shfl_xor_sync(0xffffffffu, mx1, 1));
            mx1 = fmaxf(mx1, __shfl_xor_sync(0xffffffffu, mx1, 2));
            const float mn0 = fmaxf(m_i[mt][0], mx0), mn1 = fmaxf(m_i[mt][1], mx1);
            const float cr0 = exp2f(m_i[mt][0] - mn0), cr1 = exp2f(m_i[mt][1] - mn1);
            float rs0 = 0.f, rs1 = 0.f;
            #pragma unroll
            for (int nt = 0; nt < 8; nt++) {
                s[mt][nt][0] = exp2f(s[mt][nt][0] - mn0); rs0 += s[mt][nt][0];
                s[mt][nt][1] = exp2f(s[mt][nt][1] - mn0); rs0 += s[mt][nt][1];
                s[mt][nt][2] = exp2f(s[mt][nt][2] - mn1); rs1 += s[mt][nt][2];
                s[mt][nt][3] = exp2f(s[mt][nt][3] - mn1); rs1 += s[mt][nt][3];
            }
            rs0 += __shfl_xor_sync(0xffffffffu, rs0, 1);
            rs0 += __shfl_xor_sync(0xffffffffu, rs0, 2);
            rs1 += __shfl_xor_sync(0xffffffffu, rs1, 1);
            rs1 += __shfl_xor_sync(0xffffffffu, rs1, 2);
            l_i[mt][0] = l_i[mt][0] * cr0 + rs0;
            l_i[mt][1] = l_i[mt][1] * cr1 + rs1;
            m_i[mt][0] = mn0; m_i[mt][1] = mn1;
            #pragma unroll
            for (int nt = 0; nt < 8; nt++) {
                o[mt][nt][0] *= cr0; o[mt][nt][1] *= cr0;
                o[mt][nt][2] *= cr1; o[mt][nt][3] *= cr1;
            }
            // Store P (warp-private 32-row strip), tf32-rounded
            const int pr = w * 32 + mt * 16 + g;
            #pragma unroll
            for (int nt = 0; nt < 8; nt++) {
                const int pc = nt * 8 + 2 * tq;
                Ps[pr * 68 + pc]           = f2tf(s[mt][nt][0]);
                Ps[pr * 68 + pc + 1]       = f2tf(s[mt][nt][1]);
                Ps[(pr + 8) * 68 + pc]     = f2tf(s[mt][nt][2]);
                Ps[(pr + 8) * 68 + pc + 1] = f2tf(s[mt][nt][3]);
            }
        }
        __syncwarp();

        // O += P @ V
        const unsigned* Pu = (const unsigned*)Ps;
        #pragma unroll
        for (int ks = 0; ks < 8; ks++) {
            const int kb = ks * 8;
            unsigned af[2][4];
            #pragma unroll
            for (int mt = 0; mt < 2; mt++) {
                int rr = w * 32 + mt * 16 + g;
                af[mt][0] = Pu[rr * 68 + kb + tq];
                af[mt][1] = Pu[(rr + 8) * 68 + kb + tq];
                af[mt][2] = Pu[rr * 68 + kb + tq + 4];
                af[mt][3] = Pu[(rr + 8) * 68 + kb + tq + 4];
            }
            #pragma unroll
            for (int nt = 0; nt < 8; nt++) {
                int c = nt * 8 + g;
                unsigned b0 = Vu[(kb + tq) * 72 + c];
                unsigned b1 = Vu[(kb + tq + 4) * 72 + c];
                mma8(o[0][nt], af[0], b0, b1);
                mma8(o[1][nt], af[1], b0, b1);
            }
        }

        __syncthreads();   // all warps done reading buf
        if (t + 2 < NTILES) issue_kv(t + 2, buf);
    }

    // Epilogue: normalize, round to tf32 (feeds proj GEMM), write
    #pragma unroll
    for (int mt = 0; mt < 2; mt++) {
        const float inv0 = 1.f / l_i[mt][0], inv1 = 1.f / l_i[mt][1];
        const long r0 = rowbase + q0 + w * 32 + mt * 16 + g;
        #pragma unroll
        for (int nt = 0; nt < 8; nt++) {
            const int col = h * HD + nt * 8 + 2 * tq;
            float2 v0 = { f2tf(o[mt][nt][0] * inv0), f2tf(o[mt][nt][1] * inv0) };
            float2 v1 = { f2tf(o[mt][nt][2] * inv1), f2tf(o[mt][nt][3] * inv1) };
            *(float2*)(g_att + r0 * CH + col)       = v0;
            *(float2*)(g_att + (r0 + 8) * CH + col) = v1;
        }
    }
}

// ---------------------------------------------------------------------------
extern "C" void kernel_launch(void* const* d_in, const int* in_sizes, int n_in,
                              void* d_out, int out_size)
{
    const float* x     = (const float*)d_in[0];
    const float* Wqkv  = (const float*)d_in[1];
    const float* bqkv  = (const float*)d_in[2];
    const float* Wproj = (const float*)d_in[3];
    const float* bproj = (const float*)d_in[4];
    float* out = (float*)d_out;

    float *xr, *qkv_ptr, *att_ptr, *wqkvT, *wprojT;
    cudaGetSymbolAddress((void**)&xr, g_x);
    cudaGetSymbolAddress((void**)&qkv_ptr, g_qkv);
    cudaGetSymbolAddress((void**)&att_ptr, g_att);
    cudaGetSymbolAddress((void**)&wqkvT, g_wqkvT);
    cudaGetSymbolAddress((void**)&wprojT, g_wprojT);

    static int smem_set = 0;
    const int gemm_smem  = 4 * GTILE * sizeof(float);     // 73728 B
    const int flash_smem = FL_WORDS * sizeof(float);      // 210944 B
    if (!smem_set) {
        cudaFuncSetAttribute(gemm_tc<true>,
            cudaFuncAttributeMaxDynamicSharedMemorySize, gemm_smem);
        cudaFuncSetAttribute(gemm_tc<false>,
            cudaFuncAttributeMaxDynamicSharedMemorySize, gemm_smem);
        cudaFuncSetAttribute(flash_tf32,
            cudaFuncAttributeMaxDynamicSharedMemorySize, flash_smem);
        smem_set = 1;
    }

    // Pre-round x; transpose + round weights
    round_kernel<<<(MTOT * CH) / 1024, 256>>>(x, xr);
    transpose_kernel<<<dim3(C3 / 32, CH / 32), 256>>>(Wqkv, wqkvT, CH, C3);
    transpose_kernel<<<dim3(CH / 32, CH / 32), 256>>>(Wproj, wprojT, CH, CH);

    // QKV projection (tf32-rounded output)
    gemm_tc<true><<<dim3(C3 / 128, MTOT / 128), 256, gemm_smem>>>(
        xr, wqkvT, bqkv, qkv_ptr, MTOT, C3, CH);
    // Flash attention (Br=256, double-buffered KV)
    flash_tf32<<<dim3(SEQ / BR, BATCH * NHEADS), 256, flash_smem>>>();
    // Output projection (full fp32 output)
    gemm_tc<false><<<dim3(CH / 128, MTOT / 128), 256, gemm_smem>>>(
        att_ptr, wprojT, bproj, out, MTOT, CH, CH);
}

// round 6
// speedup vs baseline: 1.0693x; 1.0693x over previous
#include <cuda_runtime.h>
#include <cstdint>
#include <math.h>

#define BATCH 4
#define SEQ 2048
#define CH 768
#define NHEADS 12
#define HD 64
#define MTOT (BATCH * SEQ)   // 8192
#define C3 (3 * CH)          // 2304

// Scratch (allocation-free contract)
__device__ float g_x[(size_t)MTOT * CH];       // tf32-rounded x
__device__ float g_qkv[(size_t)MTOT * C3];     // tf32-rounded qkv
__device__ float g_att[(size_t)MTOT * CH];     // tf32-rounded attn out
__device__ float g_wqkvT[(size_t)C3 * CH];     // Wqkv^T, tf32-rounded
__device__ float g_wprojT[(size_t)CH * CH];    // Wproj^T, tf32-rounded

__device__ __forceinline__ uint32_t smem_u32(const void* p) {
    uint32_t a;
    asm("{ .reg .u64 t; cvta.to.shared.u64 t, %1; cvt.u32.u64 %0, t; }"
        : "=r"(a) : "l"(p));
    return a;
}
__device__ __forceinline__ float f2tf(float x) {
    unsigned u;
    asm("cvt.rna.tf32.f32 %0, %1;" : "=r"(u) : "f"(x));
    return __uint_as_float(u);
}
#define CP16(dst, src) \
    asm volatile("cp.async.cg.shared.global [%0], [%1], 16;" \
                 :: "r"(dst), "l"(src) : "memory")
#define CP_COMMIT() asm volatile("cp.async.commit_group;" ::: "memory")
#define CP_WAIT(n)  asm volatile("cp.async.wait_group %0;" :: "n"(n) : "memory")

// m16n8k8 tf32 mma, fp32 accumulate in-place.
__device__ __forceinline__ void mma8(float* c, const unsigned* a,
                                     unsigned b0, unsigned b1) {
    asm volatile(
        "mma.sync.aligned.m16n8k8.row.col.f32.tf32.tf32.f32 "
        "{%0,%1,%2,%3}, {%4,%5,%6,%7}, {%8,%9}, {%0,%1,%2,%3};"
        : "+f"(c[0]), "+f"(c[1]), "+f"(c[2]), "+f"(c[3])
        : "r"(a[0]), "r"(a[1]), "r"(a[2]), "r"(a[3]), "r"(b0), "r"(b1));
}
// ldmatrix x4 on 32-bit data (each m8n8.b16 matrix == one 8x4 tile of b32)
__device__ __forceinline__ void ldsm4(unsigned& r0, unsigned& r1,
                                      unsigned& r2, unsigned& r3,
                                      uint32_t addr) {
    asm volatile("ldmatrix.sync.aligned.m8n8.x4.shared.b16 {%0,%1,%2,%3}, [%4];"
                 : "=r"(r0), "=r"(r1), "=r"(r2), "=r"(r3) : "r"(addr));
}

// ---------------------------------------------------------------------------
// Prepass: round x to tf32
// ---------------------------------------------------------------------------
__global__ __launch_bounds__(256) void round_kernel(
    const float* __restrict__ in, float* __restrict__ outp)
{
    const int idx = blockIdx.x * 256 + threadIdx.x;
    float4 v = ((const float4*)in)[idx];
    float4 o = { f2tf(v.x), f2tf(v.y), f2tf(v.z), f2tf(v.w) };
    ((float4*)outp)[idx] = o;
}

// ---------------------------------------------------------------------------
// Weight transpose with tf32 rounding: Wt[n][k] = round(W[k][n])
// ---------------------------------------------------------------------------
__global__ __launch_bounds__(256) void transpose_kernel(
    const float* __restrict__ W, float* __restrict__ Wt, int R, int Cc)
{
    __shared__ float t[32][33];
    const int bx = blockIdx.x * 32, by = blockIdx.y * 32;
    const int x = threadIdx.x & 31, y4 = (threadIdx.x >> 5) * 4;
    #pragma unroll
    for (int j = 0; j < 4; j++)
        t[y4 + j][x] = W[(long)(by + y4 + j) * Cc + bx + x];
    __syncthreads();
    #pragma unroll
    for (int j = 0; j < 4; j++)
        Wt[(long)(bx + y4 + j) * R + by + x] = f2tf(t[x][y4 + j]);
}

// ---------------------------------------------------------------------------
// tf32 mma.sync GEMM + bias, ldmatrix operand feed.
// 128x128 CTA tile, BK=32, 256 threads (8 warps 4x2, warp tile 32x64),
// cp.async double-buffered, 2 CTAs/SM.
// A-frag LDSM map: lane -> row (lane&15), col (lane>>4)*4   [stride 36 words]
// B-frag LDSM map: lane -> row (lane&7)+(lane>>4)*8, col (lane&8)?4:0
// ---------------------------------------------------------------------------
#define GSTRIDE 36
#define GTILE (128 * GSTRIDE)

template <bool ROUND>
__global__ __launch_bounds__(256, 2) void gemm_tc(
    const float* __restrict__ A, const float* __restrict__ Bt,
    const float* __restrict__ bias, float* __restrict__ C,
    int M, int N, int K)
{
    extern __shared__ float gsm[];
    const int tid = threadIdx.x;
    const int lane = tid & 31, wid = tid >> 5;
    const int g = lane >> 2, tq = lane & 3;
    const int wm = (wid & 3) * 32, wn = (wid >> 2) * 64;
    const int bm = blockIdx.y * 128, bn = blockIdx.x * 128;
    const int sr = tid >> 3, sc4 = (tid & 7) * 4;

    // per-thread ldmatrix base addresses (byte units), buffer 0
    const uint32_t sbase = smem_u32(gsm);
    const uint32_t a_base0 = sbase +
        ((wm + (lane & 15)) * GSTRIDE + (lane >> 4) * 4) * 4;
    const uint32_t b_base0 = sbase + GTILE * 4 +
        ((wn + (lane & 7) + (lane >> 4) * 8) * GSTRIDE + ((lane & 8) ? 4 : 0)) * 4;

    float acc[2][8][4];
    #pragma unroll
    for (int mt = 0; mt < 2; mt++)
        #pragma unroll
        for (int nt = 0; nt < 8; nt++)
            #pragma unroll
            for (int j = 0; j < 4; j++) acc[mt][nt][j] = 0.f;

    const int NK = K / 32;
    auto issue = [&](int kt, int b) {
        float* As = gsm + b * 2 * GTILE;
        float* Bs = As + GTILE;
        const int k0 = kt * 32;
        #pragma unroll
        for (int i = 0; i < 4; i++) {
            int r = sr + 32 * i;
            CP16(smem_u32(As + r * GSTRIDE + sc4),
                 A + (long)(bm + r) * K + k0 + sc4);
            CP16(smem_u32(Bs + r * GSTRIDE + sc4),
                 Bt + (long)(bn + r) * K + k0 + sc4);
        }
        CP_COMMIT();
    };

    issue(0, 0);
    for (int kt = 0; kt < NK; kt++) {
        const int buf = kt & 1;
        if (kt + 1 < NK) { issue(kt + 1, buf ^ 1); CP_WAIT(1); }
        else             { CP_WAIT(0); }
        __syncthreads();

        const uint32_t a_buf = a_base0 + buf * 2 * GTILE * 4;
        const uint32_t b_buf = b_base0 + buf * 2 * GTILE * 4;
        #pragma unroll
        for (int ks = 0; ks < 4; ks++) {
            unsigned af[2][4];
            ldsm4(af[0][0], af[0][1], af[0][2], af[0][3], a_buf + ks * 32);
            ldsm4(af[1][0], af[1][1], af[1][2], af[1][3],
                  a_buf + 16 * GSTRIDE * 4 + ks * 32);
            #pragma unroll
            for (int ntp = 0; ntp < 4; ntp++) {
                unsigned b0, b1, c0, c1;
                ldsm4(b0, b1, c0, c1, b_buf + ntp * 16 * GSTRIDE * 4 + ks * 32);
                mma8(acc[0][2 * ntp],     af[0], b0, b1);
                mma8(acc[1][2 * ntp],     af[1], b0, b1);
                mma8(acc[0][2 * ntp + 1], af[0], c0, c1);
                mma8(acc[1][2 * ntp + 1], af[1], c0, c1);
            }
        }
        __syncthreads();
    }

    #pragma unroll
    for (int mt = 0; mt < 2; mt++) {
        const long r0 = bm + wm + mt * 16 + g;
        #pragma unroll
        for (int nt = 0; nt < 8; nt++) {
            const int col = bn + wn + nt * 8 + 2 * tq;
            const float bz0 = bias[col], bz1 = bias[col + 1];
            float2 v0 = { acc[mt][nt][0] + bz0, acc[mt][nt][1] + bz1 };
            float2 v1 = { acc[mt][nt][2] + bz0, acc[mt][nt][3] + bz1 };
            if (ROUND) {
                v0.x = f2tf(v0.x); v0.y = f2tf(v0.y);
                v1.x = f2tf(v1.x); v1.y = f2tf(v1.y);
            }
            *(float2*)(C + r0 * N + col)       = v0;
            *(float2*)(C + (r0 + 8) * N + col) = v1;
        }
    }
}

// ---------------------------------------------------------------------------
// Flash attention (R4 shape): Br=128, Bc=64, 128 threads (4 warps), 2 CTAs/SM.
// ldmatrix for Q/K/P fragments; V fragments scalar LDS (stride-72 layout).
// Base-2 online softmax, scale*log2e folded into Q staging.
// ---------------------------------------------------------------------------
#define QS_OFF 0
#define PS_OFF (128 * 68)
#define KS_OFF (2 * 128 * 68)
#define VS_OFF (2 * 128 * 68 + 64 * 68)
#define FL_WORDS (2 * 128 * 68 + 64 * 68 + 64 * 72)   // 105472 B

__global__ __launch_bounds__(128, 2) void flash_tf32()
{
    extern __shared__ float sm[];
    float* Qs = sm + QS_OFF;
    float* Ps = sm + PS_OFF;
    float* Ks = sm + KS_OFF;
    float* Vs = sm + VS_OFF;

    const int tid = threadIdx.x;
    const int lane = tid & 31, w = tid >> 5;
    const int g = lane >> 2, tq = lane & 3;
    const int b = blockIdx.y / NHEADS, h = blockIdx.y % NHEADS;
    const int q0 = blockIdx.x * 128;
    const long rowbase = (long)b * SEQ;
    const float kscale = 0.125f * 1.44269504089f;   // 1/sqrt(d) * log2(e)

    // ldmatrix base addresses (A-side stride 68, B-side stride 68)
    const uint32_t q_base = smem_u32(Qs) +
        ((w * 32 + (lane & 15)) * 68 + (lane >> 4) * 4) * 4;
    const uint32_t p_base = smem_u32(Ps) +
        ((w * 32 + (lane & 15)) * 68 + (lane >> 4) * 4) * 4;
    const uint32_t k_base = smem_u32(Ks) +
        (((lane & 7) + (lane >> 4) * 8) * 68 + ((lane & 8) ? 4 : 0)) * 4;

    // Stage Q (scale folded, re-rounded to tf32)
    #pragma unroll
    for (int i = 0; i < 16; i++) {
        int idx = tid + 128 * i;
        int r = idx >> 4, c4 = (idx & 15) * 4;
        float4 v = *(const float4*)&g_qkv[(rowbase + q0 + r) * C3 + h * HD + c4];
        float* d = Qs + r * 68 + c4;
        d[0] = f2tf(v.x * kscale); d[1] = f2tf(v.y * kscale);
        d[2] = f2tf(v.z * kscale); d[3] = f2tf(v.w * kscale);
    }

    float o[2][8][4];
    float m_i[2][2], l_i[2][2];
    #pragma unroll
    for (int mt = 0; mt < 2; mt++) {
        m_i[mt][0] = m_i[mt][1] = -1e30f;
        l_i[mt][0] = l_i[mt][1] = 0.f;
        #pragma unroll
        for (int nt = 0; nt < 8; nt++)
            #pragma unroll
            for (int j = 0; j < 4; j++) o[mt][nt][j] = 0.f;
    }

    for (int k0 = 0; k0 < SEQ; k0 += 64) {
        __syncthreads();
        #pragma unroll
        for (int i = 0; i < 8; i++) {
            int idx = tid + 128 * i;
            int r = idx >> 4, c4 = (idx & 15) * 4;
            long gb = (rowbase + k0 + r) * C3 + h * HD + c4;
            CP16(smem_u32(Ks + r * 68 + c4), &g_qkv[gb + CH]);
            CP16(smem_u32(Vs + r * 72 + c4), &g_qkv[gb + 2 * CH]);
        }
        CP_COMMIT();
        CP_WAIT(0);
        __syncthreads();

        // S = Q @ K^T
        float s[2][8][4];
        #pragma unroll
        for (int mt = 0; mt < 2; mt++)
            #pragma unroll
            for (int nt = 0; nt < 8; nt++)
                #pragma unroll
                for (int j = 0; j < 4; j++) s[mt][nt][j] = 0.f;
        #pragma unroll
        for (int ks = 0; ks < 8; ks++) {
            unsigned af[2][4];
            ldsm4(af[0][0], af[0][1], af[0][2], af[0][3], q_base + ks * 32);
            ldsm4(af[1][0], af[1][1], af[1][2], af[1][3],
                  q_base + 16 * 68 * 4 + ks * 32);
            #pragma unroll
            for (int ntp = 0; ntp < 4; ntp++) {
                unsigned b0, b1, c0, c1;
                ldsm4(b0, b1, c0, c1, k_base + ntp * 16 * 68 * 4 + ks * 32);
                mma8(s[0][2 * ntp],     af[0], b0, b1);
                mma8(s[1][2 * ntp],     af[1], b0, b1);
                mma8(s[0][2 * ntp + 1], af[0], c0, c1);
                mma8(s[1][2 * ntp + 1], af[1], c0, c1);
            }
        }

        // Online softmax (base-2) per 16-row sub-tile
        #pragma unroll
        for (int mt = 0; mt < 2; mt++) {
            float mx0 = -1e30f, mx1 = -1e30f;
            #pragma unroll
            for (int nt = 0; nt < 8; nt++) {
                mx0 = fmaxf(mx0, fmaxf(s[mt][nt][0], s[mt][nt][1]));
                mx1 = fmaxf(mx1, fmaxf(s[mt][nt][2], s[mt][nt][3]));
            }
            mx0 = fmaxf(mx0, __shfl_xor_sync(0xffffffffu, mx0, 1));
            mx0 = fmaxf(mx0, __shfl_xor_sync(0xffffffffu, mx0, 2));
            mx1 = fmaxf(mx1, __shfl_xor_sync(0xffffffffu, mx1, 1));
            mx1 = fmaxf(mx1, __shfl_xor_sync(0xffffffffu, mx1, 2));
            const float mn0 = fmaxf(m_i[mt][0], mx0), mn1 = fmaxf(m_i[mt][1], mx1);
            const float cr0 = exp2f(m_i[mt][0] - mn0), cr1 = exp2f(m_i[mt][1] - mn1);
            float rs0 = 0.f, rs1 = 0.f;
            #pragma unroll
            for (int nt = 0; nt < 8; nt++) {
                s[mt][nt][0] = exp2f(s[mt][nt][0] - mn0); rs0 += s[mt][nt][0];
                s[mt][nt][1] = exp2f(s[mt][nt][1] - mn0); rs0 += s[mt][nt][1];
                s[mt][nt][2] = exp2f(s[mt][nt][2] - mn1); rs1 += s[mt][nt][2];
                s[mt][nt][3] = exp2f(s[mt][nt][3] - mn1); rs1 += s[mt][nt][3];
            }
            rs0 += __shfl_xor_sync(0xffffffffu, rs0, 1);
            rs0 += __shfl_xor_sync(0xffffffffu, rs0, 2);
            rs1 += __shfl_xor_sync(0xffffffffu, rs1, 1);
            rs1 += __shfl_xor_sync(0xffffffffu, rs1, 2);
            l_i[mt][0] = l_i[mt][0] * cr0 + rs0;
            l_i[mt][1] = l_i[mt][1] * cr1 + rs1;
            m_i[mt][0] = mn0; m_i[mt][1] = mn1;
            #pragma unroll
            for (int nt = 0; nt < 8; nt++) {
                o[mt][nt][0] *= cr0; o[mt][nt][1] *= cr0;
                o[mt][nt][2] *= cr1; o[mt][nt][3] *= cr1;
            }
            // Store P (warp-private strip), tf32-rounded, STS.64
            const int pr = w * 32 + mt * 16 + g;
            #pragma unroll
            for (int nt = 0; nt < 8; nt++) {
                const int pc = nt * 8 + 2 * tq;
                float2 p0 = { f2tf(s[mt][nt][0]), f2tf(s[mt][nt][1]) };
                float2 p1 = { f2tf(s[mt][nt][2]), f2tf(s[mt][nt][3]) };
                *(float2*)(Ps + pr * 68 + pc)       = p0;
                *(float2*)(Ps + (pr + 8) * 68 + pc) = p1;
            }
        }
        __syncwarp();

        // O += P @ V  (P via ldmatrix, V scalar LDS)
        const unsigned* Vu = (const unsigned*)Vs;
        #pragma unroll
        for (int ks = 0; ks < 8; ks++) {
            const int kb = ks * 8;
            unsigned af[2][4];
            ldsm4(af[0][0], af[0][1], af[0][2], af[0][3], p_base + ks * 32);
            ldsm4(af[1][0], af[1][1], af[1][2], af[1][3],
                  p_base + 16 * 68 * 4 + ks * 32);
            #pragma unroll
            for (int nt = 0; nt < 8; nt++) {
                int c = nt * 8 + g;
                unsigned b0 = Vu[(kb + tq) * 72 + c];
                unsigned b1 = Vu[(kb + tq + 4) * 72 + c];
                mma8(o[0][nt], af[0], b0, b1);
                mma8(o[1][nt], af[1], b0, b1);
            }
        }
    }

    // Epilogue: normalize, round to tf32 (feeds proj GEMM), write
    #pragma unroll
    for (int mt = 0; mt < 2; mt++) {
        const float inv0 = 1.f / l_i[mt][0], inv1 = 1.f / l_i[mt][1];
        const long r0 = rowbase + q0 + w * 32 + mt * 16 + g;
        #pragma unroll
        for (int nt = 0; nt < 8; nt++) {
            const int col = h * HD + nt * 8 + 2 * tq;
            float2 v0 = { f2tf(o[mt][nt][0] * inv0), f2tf(o[mt][nt][1] * inv0) };
            float2 v1 = { f2tf(o[mt][nt][2] * inv1), f2tf(o[mt][nt][3] * inv1) };
            *(float2*)(g_att + r0 * CH + col)       = v0;
            *(float2*)(g_att + (r0 + 8) * CH + col) = v1;
        }
    }
}

// ---------------------------------------------------------------------------
extern "C" void kernel_launch(void* const* d_in, const int* in_sizes, int n_in,
                              void* d_out, int out_size)
{
    const float* x     = (const float*)d_in[0];
    const float* Wqkv  = (const float*)d_in[1];
    const float* bqkv  = (const float*)d_in[2];
    const float* Wproj = (const float*)d_in[3];
    const float* bproj = (const float*)d_in[4];
    float* out = (float*)d_out;

    float *xr, *qkv_ptr, *att_ptr, *wqkvT, *wprojT;
    cudaGetSymbolAddress((void**)&xr, g_x);
    cudaGetSymbolAddress((void**)&qkv_ptr, g_qkv);
    cudaGetSymbolAddress((void**)&att_ptr, g_att);
    cudaGetSymbolAddress((void**)&wqkvT, g_wqkvT);
    cudaGetSymbolAddress((void**)&wprojT, g_wprojT);

    static int smem_set = 0;
    const int gemm_smem  = 4 * GTILE * sizeof(float);     // 73728 B
    const int flash_smem = FL_WORDS * sizeof(float);      // 105472 B
    if (!smem_set) {
        cudaFuncSetAttribute(gemm_tc<true>,
            cudaFuncAttributeMaxDynamicSharedMemorySize, gemm_smem);
        cudaFuncSetAttribute(gemm_tc<false>,
            cudaFuncAttributeMaxDynamicSharedMemorySize, gemm_smem);
        cudaFuncSetAttribute(flash_tf32,
            cudaFuncAttributeMaxDynamicSharedMemorySize, flash_smem);
        smem_set = 1;
    }

    // Pre-round x; transpose + round weights
    round_kernel<<<(MTOT * CH) / 1024, 256>>>(x, xr);
    transpose_kernel<<<dim3(C3 / 32, CH / 32), 256>>>(Wqkv, wqkvT, CH, C3);
    transpose_kernel<<<dim3(CH / 32, CH / 32), 256>>>(Wproj, wprojT, CH, CH);

    // QKV projection (tf32-rounded output)
    gemm_tc<true><<<dim3(C3 / 128, MTOT / 128), 256, gemm_smem>>>(
        xr, wqkvT, bqkv, qkv_ptr, MTOT, C3, CH);
    // Flash attention (Br=128, 2 CTAs/SM, ldmatrix feed)
    flash_tf32<<<dim3(SEQ / 128, BATCH * NHEADS), 128, flash_smem>>>();
    // Output projection (full fp32 output)
    gemm_tc<false><<<dim3(CH / 128, MTOT / 128), 256, gemm_smem>>>(
        att_ptr, wprojT, bproj, out, MTOT, CH, CH);
}